// round 6
// baseline (speedup 1.0000x reference)
#include <cuda_runtime.h>
#include <math.h>

#define NN   50000
#define EE   500000
#define DD   128
#define BB   50
#define NPG  1000
#define KSEL 500
#define BK   (BB*KSEL)
#define ALPHA_F 0.6f

typedef unsigned long long ull;

#define FMA_F32X2(d, a, b, c) \
    asm("fma.rn.f32x2 %0, %1, %2, %3;" : "=l"(d) : "l"(a), "l"(b), "l"(c))

__device__ int   g_deg[NN];
__device__ float g_dinv[NN];
__device__ float g_ds[NN];
__device__ float g_zs[NN];
__device__ float g_sf[NN];
__device__ float g_score[NN];
__device__ int   g_perm[BK];
__device__ int   g_nodemap[NN];
__device__ int   g_off[NN];
__device__ int   g_cursor[NN];
__device__ int   g_csr[EE];
__device__ int   g_total;
__device__ int   g_bsum[512];
__device__ int   g_boff[512];

__global__ void k_init() {
    int i = blockIdx.x * blockDim.x + threadIdx.x;
    int stride = gridDim.x * blockDim.x;
    if (i == 0) g_total = 0;
    for (int t = i; t < NN; t += stride) g_deg[t] = 0;
}

__global__ void k_deg(const int* __restrict__ dst) {
    int i = blockIdx.x * blockDim.x + threadIdx.x;
    if (i < EE / 4) {
        int4 d4 = ((const int4*)dst)[i];
        atomicAdd(&g_deg[d4.x], 1);
        atomicAdd(&g_deg[d4.y], 1);
        atomicAdd(&g_deg[d4.z], 1);
        atomicAdd(&g_deg[d4.w], 1);
    }
}

__global__ void k_scores(const float* __restrict__ x, const float* __restrict__ Ws,
                         const float* __restrict__ Wf, const float* __restrict__ bf) {
    int warp = (blockIdx.x * blockDim.x + threadIdx.x) >> 5;
    int lane = threadIdx.x & 31;
    if (warp >= NN) return;
    float4 xv = ((const float4*)x)[warp * 32 + lane];
    float4 ws = ((const float4*)Ws)[lane];
    float4 wf = ((const float4*)Wf)[lane];
    float ds = xv.x*ws.x + xv.y*ws.y + xv.z*ws.z + xv.w*ws.w;
    float df = xv.x*wf.x + xv.y*wf.y + xv.z*wf.z + xv.w*wf.w;
    #pragma unroll
    for (int o = 16; o > 0; o >>= 1) {
        ds += __shfl_down_sync(0xffffffffu, ds, o);
        df += __shfl_down_sync(0xffffffffu, df, o);
    }
    if (lane == 0) {
        g_ds[warp] = ds;
        g_sf[warp] = df + bf[0];
    }
}

__global__ void k_offsets() {
    __shared__ int wpref[8];
    int tid = threadIdx.x;
    int n = blockIdx.x * 256 + tid;
    int d = (n < NN) ? g_deg[n] : 0;
    int lane = tid & 31, wid = tid >> 5;
    int v = d;
    #pragma unroll
    for (int o = 1; o < 32; o <<= 1) {
        int u = __shfl_up_sync(0xffffffffu, v, o);
        if (lane >= o) v += u;
    }
    if (lane == 31) wpref[wid] = v;
    __syncthreads();
    if (tid == 0) {
        int t[8], run = 0;
        #pragma unroll
        for (int w = 0; w < 8; w++) { t[w] = run; run += wpref[w]; }
        int base = atomicAdd(&g_total, run);
        #pragma unroll
        for (int w = 0; w < 8; w++) wpref[w] = base + t[w];
    }
    __syncthreads();
    int off = wpref[wid] + (v - d);
    if (n < NN) {
        g_off[n]    = off;
        g_cursor[n] = off;
        float dv = rsqrtf((float)(d + 1));
        g_dinv[n] = dv;
        g_zs[n]   = dv * g_ds[n];
        g_nodemap[n] = -1;
    }
}

__global__ void k_csr(const int* __restrict__ src, const int* __restrict__ dst) {
    int i = blockIdx.x * blockDim.x + threadIdx.x;
    if (i < EE / 8) {
        int4 s4 = ((const int4*)src)[2*i];
        int4 d4 = ((const int4*)dst)[2*i];
        int4 s5 = ((const int4*)src)[2*i+1];
        int4 d5 = ((const int4*)dst)[2*i+1];
        g_csr[atomicAdd(&g_cursor[d4.x], 1)] = s4.x;
        g_csr[atomicAdd(&g_cursor[d4.y], 1)] = s4.y;
        g_csr[atomicAdd(&g_cursor[d4.z], 1)] = s4.z;
        g_csr[atomicAdd(&g_cursor[d4.w], 1)] = s4.w;
        g_csr[atomicAdd(&g_cursor[d5.x], 1)] = s5.x;
        g_csr[atomicAdd(&g_cursor[d5.y], 1)] = s5.y;
        g_csr[atomicAdd(&g_cursor[d5.z], 1)] = s5.z;
        g_csr[atomicAdd(&g_cursor[d5.w], 1)] = s5.w;
    }
}

__global__ void k_gather_score(const float* __restrict__ bs) {
    int n = blockIdx.x * blockDim.x + threadIdx.x;
    if (n >= NN) return;
    int beg = g_off[n], len = g_deg[n];
    float sum = g_zs[n];
    #pragma unroll 4
    for (int i = 0; i < len; i++)
        sum += g_zs[g_csr[beg + i]];
    float ss = g_dinv[n] * sum + bs[0];
    g_score[n] = tanhf(ALPHA_F * ss + (1.0f - ALPHA_F) * g_sf[n]);
}

__global__ void k_topk(float* __restrict__ out, long permOff, long batchOff) {
    __shared__ __align__(16) ull sk[NPG];
    int b = blockIdx.x >> 2;
    int quarter = blockIdx.x & 3;
    int tid = threadIdx.x;
    for (int i = tid; i < NPG; i += 256) {
        int iv = __float_as_int(g_score[b * NPG + i]);
        unsigned u = (unsigned)iv ^ ((unsigned)(iv >> 31) | 0x80000000u);
        sk[i] = ((ull)u << 32) | (unsigned)(~i);
    }
    __syncthreads();
    int j = quarter * 256 + tid;
    if (j >= NPG) return;
    ull myk = sk[j];
    int rank = 0;
    const ulonglong2* p2 = (const ulonglong2*)sk;
    #pragma unroll 4
    for (int i2 = 0; i2 < NPG / 2; i2++) {
        ulonglong2 kv = p2[i2];
        rank += (kv.x > myk);
        rank += (kv.y > myk);
    }
    if (rank < KSEL) {
        int p  = b * NPG + j;
        int gi = b * KSEL + rank;
        g_perm[gi]   = p;
        g_nodemap[p] = gi;
        out[permOff  + gi] = (float)p;
        out[batchOff + gi] = (float)b;
    }
}

#define SA_S 130
#define SB_S 34
__global__ void __launch_bounds__(256, 2)
k_gemm(const float* __restrict__ x, const float* __restrict__ W,
       const float* __restrict__ bfu, float* __restrict__ out, long xaeOff) {
    __shared__ __align__(16) float sA[64 * SA_S];
    __shared__ __align__(16) float sBT[DD * SB_S];
    __shared__ float sScore[64];

    int tid  = threadIdx.x;
    int lane = tid & 31, wid = tid >> 5;
    int row0 = blockIdx.x * 64;

    if (tid < 64) {
        int r = row0 + tid;
        sScore[tid] = (r < BK) ? g_score[g_perm[r]] : 0.f;
    }

    #pragma unroll
    for (int i = 0; i < 8; i++) {
        int r = wid * 8 + i;
        int grow = row0 + r;
        float4 acc = make_float4(0.f, 0.f, 0.f, 0.f);
        if (grow < BK) {
            int   p   = g_perm[grow];
            float dvp = g_dinv[p];
            float4 xv = ((const float4*)x)[p * 32 + lane];
            acc = make_float4(dvp*xv.x, dvp*xv.y, dvp*xv.z, dvp*xv.w);
            int beg = g_off[p], len = g_deg[p];
            for (int base = 0; base < len; base += 32) {
                int idx = base + lane;
                int   s  = (idx < len) ? g_csr[beg + idx] : 0;
                float dv = (idx < len) ? g_dinv[s] : 0.f;
                int cnt = min(32, len - base);
                for (int j = 0; j < cnt; j++) {
                    int   sj = __shfl_sync(0xffffffffu, s,  j);
                    float dj = __shfl_sync(0xffffffffu, dv, j);
                    float4 xs = ((const float4*)x)[sj * 32 + lane];
                    acc.x += dj * xs.x;
                    acc.y += dj * xs.y;
                    acc.z += dj * xs.z;
                    acc.w += dj * xs.w;
                }
            }
            acc.x *= dvp; acc.y *= dvp; acc.z *= dvp; acc.w *= dvp;
        }
        // row stride SA_S=130 floats (520B, 8B-aligned); lane*4 floats = 16B-aligned.
        // base is __align__(16): every float4 store lands 8B-aligned or better; the
        // 16B requirement holds because 130*r*4 + lane*16 ≡ 8r (mod 16)... use float2.
        *(float2*)&sA[r * SA_S + lane * 4]     = make_float2(acc.x, acc.y);
        *(float2*)&sA[r * SA_S + lane * 4 + 2] = make_float2(acc.z, acc.w);
    }

    ull acc2[8][4];
    #pragma unroll
    for (int i = 0; i < 8; i++)
        #pragma unroll
        for (int q = 0; q < 4; q++) acc2[i][q] = 0ull;

    int tx = lane, ty = wid;

    for (int kk = 0; kk < DD; kk += 32) {
        #pragma unroll
        for (int q = tid; q < 1024; q += 256) {
            int k  = q >> 5;
            int c4 = (q & 31) * 4;
            float4 w4 = *(const float4*)&W[(long)(kk + k) * DD + c4];
            sBT[(c4 + 0) * SB_S + k] = w4.x;
            sBT[(c4 + 1) * SB_S + k] = w4.y;
            sBT[(c4 + 2) * SB_S + k] = w4.z;
            sBT[(c4 + 3) * SB_S + k] = w4.w;
        }
        __syncthreads();
        #pragma unroll
        for (int k2 = 0; k2 < 16; k2++) {
            ull b2[4];
            #pragma unroll
            for (int q = 0; q < 4; q++)
                b2[q] = *(const ull*)&sBT[(tx + 32 * q) * SB_S + 2 * k2];
            #pragma unroll
            for (int i = 0; i < 8; i++) {
                ull a2 = *(const ull*)&sA[(ty * 8 + i) * SA_S + kk + 2 * k2];
                #pragma unroll
                for (int q = 0; q < 4; q++)
                    FMA_F32X2(acc2[i][q], a2, b2[q], acc2[i][q]);
            }
        }
        __syncthreads();
    }

    float bq[4];
    #pragma unroll
    for (int q = 0; q < 4; q++) bq[q] = bfu[tx + 32 * q];
    #pragma unroll
    for (int i = 0; i < 8; i++) {
        int r = ty * 8 + i;
        int grow = row0 + r;
        if (grow < BK) {
            float sc = sScore[r];
            long base = (long)grow * DD;
            #pragma unroll
            for (int q = 0; q < 4; q++) {
                float lo, hi;
                asm("mov.b64 {%0, %1}, %2;" : "=f"(lo), "=f"(hi) : "l"(acc2[i][q]));
                float v = lo + hi + bq[q];
                int col = tx + 32 * q;
                out[base + col]          = v * sc;
                out[xaeOff + base + col] = v;
            }
        }
    }
}

#define SCAN_T 256
#define SCAN_I 8
#define SCAN_B ((EE + SCAN_T*SCAN_I - 1) / (SCAN_T*SCAN_I))

__global__ void k_flag(const int* __restrict__ src, const int* __restrict__ dst) {
    __shared__ int wsum[8];
    int tid = threadIdx.x;
    int base = blockIdx.x * SCAN_T * SCAN_I + tid * SCAN_I;
    int cnt = 0;
    #pragma unroll
    for (int t = 0; t < SCAN_I; t++) {
        int e = base + t;
        if (e < EE && g_nodemap[src[e]] >= 0 && g_nodemap[dst[e]] >= 0) cnt++;
    }
    int lane = tid & 31, wid = tid >> 5;
    int v = cnt;
    #pragma unroll
    for (int o = 16; o > 0; o >>= 1) v += __shfl_down_sync(0xffffffffu, v, o);
    if (lane == 0) wsum[wid] = v;
    __syncthreads();
    if (tid == 0) {
        int tot = 0;
        for (int w = 0; w < 8; w++) tot += wsum[w];
        g_bsum[blockIdx.x] = tot;
    }
}

__global__ void k_scan() {
    if (threadIdx.x == 0) {
        int run = 0;
        for (int b = 0; b < SCAN_B; b++) { g_boff[b] = run; run += g_bsum[b]; }
    }
}

__global__ void k_scatter(const int* __restrict__ src, const int* __restrict__ dst,
                          float* __restrict__ out, long edgeOff, int M) {
    __shared__ int wsum[8];
    __shared__ int woff[8];
    int tid = threadIdx.x;
    int base = blockIdx.x * SCAN_T * SCAN_I + tid * SCAN_I;
    int f[SCAN_I], r[SCAN_I], c[SCAN_I];
    int cnt = 0;
    #pragma unroll
    for (int t = 0; t < SCAN_I; t++) {
        int e = base + t;
        f[t] = 0;
        if (e < EE) {
            int rr = g_nodemap[src[e]];
            int cc = g_nodemap[dst[e]];
            if (rr >= 0 && cc >= 0) { f[t] = 1; r[t] = rr; c[t] = cc; cnt++; }
        }
    }
    int lane = tid & 31, wid = tid >> 5;
    int v = cnt;
    #pragma unroll
    for (int o = 1; o < 32; o <<= 1) {
        int u = __shfl_up_sync(0xffffffffu, v, o);
        if (lane >= o) v += u;
    }
    if (lane == 31) wsum[wid] = v;
    __syncthreads();
    if (tid == 0) {
        int run = 0;
        for (int w = 0; w < 8; w++) { woff[w] = run; run += wsum[w]; }
    }
    __syncthreads();
    int pos = (v - cnt) + woff[wid] + g_boff[blockIdx.x];
    #pragma unroll
    for (int t = 0; t < SCAN_I; t++) {
        if (f[t]) {
            out[edgeOff + pos]     = (float)r[t];
            out[edgeOff + M + pos] = (float)c[t];
            pos++;
        }
    }
}

struct AsyncRes {
    cudaStream_t s1, s2;
    cudaEvent_t evRoot, evScores, evTopk, evTail;
    AsyncRes() {
        cudaStreamCreateWithFlags(&s1, cudaStreamNonBlocking);
        cudaStreamCreateWithFlags(&s2, cudaStreamNonBlocking);
        cudaEventCreateWithFlags(&evRoot,   cudaEventDisableTiming);
        cudaEventCreateWithFlags(&evScores, cudaEventDisableTiming);
        cudaEventCreateWithFlags(&evTopk,   cudaEventDisableTiming);
        cudaEventCreateWithFlags(&evTail,   cudaEventDisableTiming);
    }
};

extern "C" void kernel_launch(void* const* d_in, const int* in_sizes, int n_in,
                              void* d_out, int out_size) {
    const float* x    = (const float*)d_in[0];
    const int*   ei   = (const int*)d_in[1];
    const float* Ws   = (const float*)d_in[3];
    const float* bs   = (const float*)d_in[4];
    const float* Wf   = (const float*)d_in[5];
    const float* bf   = (const float*)d_in[6];
    const float* Wfu  = (const float*)d_in[7];
    const float* bfu  = (const float*)d_in[8];
    float* out = (float*)d_out;

    static AsyncRes R;

    const int* src = ei;
    const int* dst = ei + EE;

    long M = ((long)out_size - (2L * BK * DD + 2L * BK)) / 2;
    long edgeOff  = (long)BK * DD;
    long batchOff = edgeOff + 2 * M;
    long permOff  = batchOff + BK;
    long xaeOff   = permOff + BK;

    cudaEventRecord(R.evRoot, 0);
    cudaStreamWaitEvent(R.s1, R.evRoot, 0);
    k_scores<<<(NN * 32 + 255) / 256, 256, 0, R.s1>>>(x, Ws, Wf, bf);
    cudaEventRecord(R.evScores, R.s1);

    k_init<<<128, 256>>>();
    k_deg<<<(EE / 4 + 255) / 256, 256>>>(dst);

    cudaStreamWaitEvent(0, R.evScores, 0);
    k_offsets<<<(NN + 255) / 256, 256>>>();
    k_csr<<<(EE / 8 + 255) / 256, 256>>>(src, dst);
    k_gather_score<<<(NN + 255) / 256, 256>>>(bs);
    k_topk<<<BB * 4, 256>>>(out, permOff, batchOff);

    cudaEventRecord(R.evTopk, 0);
    cudaStreamWaitEvent(R.s2, R.evTopk, 0);
    k_flag<<<SCAN_B, SCAN_T, 0, R.s2>>>(src, dst);
    k_scan<<<1, 32, 0, R.s2>>>();
    k_scatter<<<SCAN_B, SCAN_T, 0, R.s2>>>(src, dst, out, edgeOff, (int)M);
    cudaEventRecord(R.evTail, R.s2);

    k_gemm<<<(BK + 63) / 64, 256>>>(x, Wfu, bfu, out, xaeOff);

    cudaStreamWaitEvent(0, R.evTail, 0);
}

// round 9
// speedup vs baseline: 1.1272x; 1.1272x over previous
#include <cuda_runtime.h>
#include <math.h>

#define NN   50000
#define EE   500000
#define DD   128
#define BB   50
#define NPG  1000
#define KSEL 500
#define BK   (BB*KSEL)
#define ALPHA_F 0.6f

typedef unsigned long long ull;

__device__ int   g_deg[NN];
__device__ float g_dinv[NN];
__device__ float g_ds[NN];
__device__ float g_zs[NN];
__device__ float g_sf[NN];
__device__ float g_score[NN];
__device__ int   g_perm[BK];
__device__ int   g_nodemap[NN];
__device__ int   g_off[NN];
__device__ int   g_cursor[NN];
__device__ int   g_csr[EE];
__device__ int   g_total;
__device__ int   g_bsum[512];
__device__ int   g_boff[512];

__global__ void k_init() {
    int i = blockIdx.x * blockDim.x + threadIdx.x;
    int stride = gridDim.x * blockDim.x;
    if (i == 0) g_total = 0;
    for (int t = i; t < NN; t += stride) g_deg[t] = 0;
}

__global__ void k_deg(const int* __restrict__ dst) {
    int i = blockIdx.x * blockDim.x + threadIdx.x;
    if (i < EE / 4) {
        int4 d4 = ((const int4*)dst)[i];
        atomicAdd(&g_deg[d4.x], 1);
        atomicAdd(&g_deg[d4.y], 1);
        atomicAdd(&g_deg[d4.z], 1);
        atomicAdd(&g_deg[d4.w], 1);
    }
}

__global__ void k_scores(const float* __restrict__ x, const float* __restrict__ Ws,
                         const float* __restrict__ Wf, const float* __restrict__ bf) {
    int warp = (blockIdx.x * blockDim.x + threadIdx.x) >> 5;
    int lane = threadIdx.x & 31;
    if (warp >= NN) return;
    float4 xv = ((const float4*)x)[warp * 32 + lane];
    float4 ws = ((const float4*)Ws)[lane];
    float4 wf = ((const float4*)Wf)[lane];
    float ds = xv.x*ws.x + xv.y*ws.y + xv.z*ws.z + xv.w*ws.w;
    float df = xv.x*wf.x + xv.y*wf.y + xv.z*wf.z + xv.w*wf.w;
    #pragma unroll
    for (int o = 16; o > 0; o >>= 1) {
        ds += __shfl_down_sync(0xffffffffu, ds, o);
        df += __shfl_down_sync(0xffffffffu, df, o);
    }
    if (lane == 0) {
        g_ds[warp] = ds;
        g_sf[warp] = df + bf[0];
    }
}

__global__ void k_offsets() {
    __shared__ int wpref[8];
    int tid = threadIdx.x;
    int n = blockIdx.x * 256 + tid;
    int d = (n < NN) ? g_deg[n] : 0;
    int lane = tid & 31, wid = tid >> 5;
    int v = d;
    #pragma unroll
    for (int o = 1; o < 32; o <<= 1) {
        int u = __shfl_up_sync(0xffffffffu, v, o);
        if (lane >= o) v += u;
    }
    if (lane == 31) wpref[wid] = v;
    __syncthreads();
    if (tid == 0) {
        int t[8], run = 0;
        #pragma unroll
        for (int w = 0; w < 8; w++) { t[w] = run; run += wpref[w]; }
        int base = atomicAdd(&g_total, run);
        #pragma unroll
        for (int w = 0; w < 8; w++) wpref[w] = base + t[w];
    }
    __syncthreads();
    int off = wpref[wid] + (v - d);
    if (n < NN) {
        g_off[n]    = off;
        g_cursor[n] = off;
        float dv = rsqrtf((float)(d + 1));
        g_dinv[n] = dv;
        g_zs[n]   = dv * g_ds[n];
        g_nodemap[n] = -1;
    }
}

__global__ void k_csr(const int* __restrict__ src, const int* __restrict__ dst) {
    int i = blockIdx.x * blockDim.x + threadIdx.x;
    if (i < EE / 4) {
        int4 s4 = ((const int4*)src)[i];
        int4 d4 = ((const int4*)dst)[i];
        g_csr[atomicAdd(&g_cursor[d4.x], 1)] = s4.x;
        g_csr[atomicAdd(&g_cursor[d4.y], 1)] = s4.y;
        g_csr[atomicAdd(&g_cursor[d4.z], 1)] = s4.z;
        g_csr[atomicAdd(&g_cursor[d4.w], 1)] = s4.w;
    }
}

__global__ void k_gather_score(const float* __restrict__ bs) {
    int n = blockIdx.x * blockDim.x + threadIdx.x;
    if (n >= NN) return;
    int beg = g_off[n], len = g_deg[n];
    float sum = g_zs[n];
    #pragma unroll 4
    for (int i = 0; i < len; i++)
        sum += g_zs[g_csr[beg + i]];
    float ss = g_dinv[n] * sum + bs[0];
    g_score[n] = tanhf(ALPHA_F * ss + (1.0f - ALPHA_F) * g_sf[n]);
}

__global__ void k_topk(float* __restrict__ out, long permOff, long batchOff) {
    __shared__ __align__(16) ull sk[NPG];
    int b = blockIdx.x >> 2;
    int quarter = blockIdx.x & 3;
    int tid = threadIdx.x;
    for (int i = tid; i < NPG; i += 256) {
        int iv = __float_as_int(g_score[b * NPG + i]);
        unsigned u = (unsigned)iv ^ ((unsigned)(iv >> 31) | 0x80000000u);
        sk[i] = ((ull)u << 32) | (unsigned)(~i);
    }
    __syncthreads();
    int j = quarter * 256 + tid;
    if (j >= NPG) return;
    ull myk = sk[j];
    int rank = 0;
    const ulonglong2* p2 = (const ulonglong2*)sk;
    #pragma unroll 4
    for (int i2 = 0; i2 < NPG / 2; i2++) {
        ulonglong2 kv = p2[i2];
        rank += (kv.x > myk);
        rank += (kv.y > myk);
    }
    if (rank < KSEL) {
        int p  = b * NPG + j;
        int gi = b * KSEL + rank;
        g_perm[gi]   = p;
        g_nodemap[p] = gi;
        out[permOff  + gi] = (float)p;
        out[batchOff + gi] = (float)b;
    }
}

// ---------------- fused gather + FFMA GEMM (R4-proven structure) ----------------
#define SA_S 132   // 528B row stride: 16B-aligned row starts, odd bank offset per row
__global__ void __launch_bounds__(256)
k_gemm(const float* __restrict__ x, const float* __restrict__ W,
       const float* __restrict__ bfu, float* __restrict__ out, long xaeOff) {
    __shared__ __align__(16) float sA[64 * SA_S];   // 33.8 KB
    __shared__ __align__(16) float sB[16 * 128];    // 8 KB
    __shared__ float sScore[64];

    int tid  = threadIdx.x;
    int lane = tid & 31, wid = tid >> 5;
    int row0 = blockIdx.x * 64;

    if (tid < 64) {
        int r = row0 + tid;
        sScore[tid] = (r < BK) ? g_score[g_perm[r]] : 0.f;
    }

    // gather: warp wid builds rows wid*8 .. wid*8+7
    #pragma unroll
    for (int i = 0; i < 8; i++) {
        int r = wid * 8 + i;
        int grow = row0 + r;
        float4 acc = make_float4(0.f, 0.f, 0.f, 0.f);
        if (grow < BK) {
            int   p   = g_perm[grow];
            float dvp = g_dinv[p];
            float4 xv = ((const float4*)x)[p * 32 + lane];
            acc = make_float4(dvp*xv.x, dvp*xv.y, dvp*xv.z, dvp*xv.w);
            int beg = g_off[p], len = g_deg[p];
            for (int base = 0; base < len; base += 32) {
                int idx = base + lane;
                int   s  = (idx < len) ? g_csr[beg + idx] : 0;
                float dv = (idx < len) ? g_dinv[s] : 0.f;
                int cnt = min(32, len - base);
                for (int j = 0; j < cnt; j++) {
                    int   sj = __shfl_sync(0xffffffffu, s,  j);
                    float dj = __shfl_sync(0xffffffffu, dv, j);
                    float4 xs = ((const float4*)x)[sj * 32 + lane];
                    acc.x += dj * xs.x;
                    acc.y += dj * xs.y;
                    acc.z += dj * xs.z;
                    acc.w += dj * xs.w;
                }
            }
            acc.x *= dvp; acc.y *= dvp; acc.z *= dvp; acc.w *= dvp;
        }
        *(float4*)&sA[r * SA_S + lane * 4] = acc;   // 528r + 16*lane -> 16B aligned
    }
    __syncthreads();

    float accR[8][4] = {};
    int tx = lane, ty = wid;

    for (int kk = 0; kk < DD; kk += 16) {
        for (int q = tid; q < 512; q += 256) {
            int k = q >> 5, c4 = (q & 31) * 4;
            *(float4*)&sB[k * 128 + c4] = *(const float4*)&W[(long)(kk + k) * DD + c4];
        }
        __syncthreads();
        #pragma unroll
        for (int k = 0; k < 16; k++) {
            float4 b4 = *(float4*)&sB[k * 128 + tx * 4];
            #pragma unroll
            for (int i = 0; i < 8; i++) {
                float a = sA[(ty * 8 + i) * SA_S + kk + k];
                accR[i][0] += a * b4.x;
                accR[i][1] += a * b4.y;
                accR[i][2] += a * b4.z;
                accR[i][3] += a * b4.w;
            }
        }
        __syncthreads();
    }

    float4 bias = *(const float4*)&bfu[tx * 4];
    #pragma unroll
    for (int i = 0; i < 8; i++) {
        int r = ty * 8 + i;
        int grow = row0 + r;
        if (grow < BK) {
            float sc = sScore[r];
            float v0 = accR[i][0] + bias.x;
            float v1 = accR[i][1] + bias.y;
            float v2 = accR[i][2] + bias.z;
            float v3 = accR[i][3] + bias.w;
            long base = (long)grow * DD + tx * 4;
            *(float4*)&out[base] = make_float4(v0*sc, v1*sc, v2*sc, v3*sc);
            *(float2*)&out[xaeOff + base]     = make_float2(v0, v1);
            *(float2*)&out[xaeOff + base + 2] = make_float2(v2, v3);
        }
    }
}

#define SCAN_T 256
#define SCAN_I 8
#define SCAN_B ((EE + SCAN_T*SCAN_I - 1) / (SCAN_T*SCAN_I))

__global__ void k_flag(const int* __restrict__ src, const int* __restrict__ dst) {
    __shared__ int wsum[8];
    int tid = threadIdx.x;
    int base = blockIdx.x * SCAN_T * SCAN_I + tid * SCAN_I;
    int cnt = 0;
    #pragma unroll
    for (int t = 0; t < SCAN_I; t++) {
        int e = base + t;
        if (e < EE && g_nodemap[src[e]] >= 0 && g_nodemap[dst[e]] >= 0) cnt++;
    }
    int lane = tid & 31, wid = tid >> 5;
    int v = cnt;
    #pragma unroll
    for (int o = 16; o > 0; o >>= 1) v += __shfl_down_sync(0xffffffffu, v, o);
    if (lane == 0) wsum[wid] = v;
    __syncthreads();
    if (tid == 0) {
        int tot = 0;
        for (int w = 0; w < 8; w++) tot += wsum[w];
        g_bsum[blockIdx.x] = tot;
    }
}

__global__ void k_scan() {
    if (threadIdx.x == 0) {
        int run = 0;
        for (int b = 0; b < SCAN_B; b++) { g_boff[b] = run; run += g_bsum[b]; }
    }
}

__global__ void k_scatter(const int* __restrict__ src, const int* __restrict__ dst,
                          float* __restrict__ out, long edgeOff, int M) {
    __shared__ int wsum[8];
    __shared__ int woff[8];
    int tid = threadIdx.x;
    int base = blockIdx.x * SCAN_T * SCAN_I + tid * SCAN_I;
    int f[SCAN_I], r[SCAN_I], c[SCAN_I];
    int cnt = 0;
    #pragma unroll
    for (int t = 0; t < SCAN_I; t++) {
        int e = base + t;
        f[t] = 0;
        if (e < EE) {
            int rr = g_nodemap[src[e]];
            int cc = g_nodemap[dst[e]];
            if (rr >= 0 && cc >= 0) { f[t] = 1; r[t] = rr; c[t] = cc; cnt++; }
        }
    }
    int lane = tid & 31, wid = tid >> 5;
    int v = cnt;
    #pragma unroll
    for (int o = 1; o < 32; o <<= 1) {
        int u = __shfl_up_sync(0xffffffffu, v, o);
        if (lane >= o) v += u;
    }
    if (lane == 31) wsum[wid] = v;
    __syncthreads();
    if (tid == 0) {
        int run = 0;
        for (int w = 0; w < 8; w++) { woff[w] = run; run += wsum[w]; }
    }
    __syncthreads();
    int pos = (v - cnt) + woff[wid] + g_boff[blockIdx.x];
    #pragma unroll
    for (int t = 0; t < SCAN_I; t++) {
        if (f[t]) {
            out[edgeOff + pos]     = (float)r[t];
            out[edgeOff + M + pos] = (float)c[t];
            pos++;
        }
    }
}

struct AsyncRes {
    cudaStream_t s1, s2;
    cudaEvent_t evRoot, evScores, evTopk, evTail;
    AsyncRes() {
        cudaStreamCreateWithFlags(&s1, cudaStreamNonBlocking);
        cudaStreamCreateWithFlags(&s2, cudaStreamNonBlocking);
        cudaEventCreateWithFlags(&evRoot,   cudaEventDisableTiming);
        cudaEventCreateWithFlags(&evScores, cudaEventDisableTiming);
        cudaEventCreateWithFlags(&evTopk,   cudaEventDisableTiming);
        cudaEventCreateWithFlags(&evTail,   cudaEventDisableTiming);
    }
};

extern "C" void kernel_launch(void* const* d_in, const int* in_sizes, int n_in,
                              void* d_out, int out_size) {
    const float* x    = (const float*)d_in[0];
    const int*   ei   = (const int*)d_in[1];
    const float* Ws   = (const float*)d_in[3];
    const float* bs   = (const float*)d_in[4];
    const float* Wf   = (const float*)d_in[5];
    const float* bf   = (const float*)d_in[6];
    const float* Wfu  = (const float*)d_in[7];
    const float* bfu  = (const float*)d_in[8];
    float* out = (float*)d_out;

    static AsyncRes R;

    const int* src = ei;
    const int* dst = ei + EE;

    long M = ((long)out_size - (2L * BK * DD + 2L * BK)) / 2;
    long edgeOff  = (long)BK * DD;
    long batchOff = edgeOff + 2 * M;
    long permOff  = batchOff + BK;
    long xaeOff   = permOff + BK;

    cudaEventRecord(R.evRoot, 0);
    cudaStreamWaitEvent(R.s1, R.evRoot, 0);
    k_scores<<<(NN * 32 + 255) / 256, 256, 0, R.s1>>>(x, Ws, Wf, bf);
    cudaEventRecord(R.evScores, R.s1);

    k_init<<<128, 256>>>();
    k_deg<<<(EE / 4 + 255) / 256, 256>>>(dst);

    cudaStreamWaitEvent(0, R.evScores, 0);
    k_offsets<<<(NN + 255) / 256, 256>>>();
    k_csr<<<(EE / 4 + 255) / 256, 256>>>(src, dst);
    k_gather_score<<<(NN + 255) / 256, 256>>>(bs);
    k_topk<<<BB * 4, 256>>>(out, permOff, batchOff);

    cudaEventRecord(R.evTopk, 0);
    cudaStreamWaitEvent(R.s2, R.evTopk, 0);
    k_flag<<<SCAN_B, SCAN_T, 0, R.s2>>>(src, dst);
    k_scan<<<1, 32, 0, R.s2>>>();
    k_scatter<<<SCAN_B, SCAN_T, 0, R.s2>>>(src, dst, out, edgeOff, (int)M);
    cudaEventRecord(R.evTail, R.s2);

    k_gemm<<<(BK + 63) / 64, 256>>>(x, Wfu, bfu, out, xaeOff);

    cudaStreamWaitEvent(0, R.evTail, 0);
}

// round 10
// speedup vs baseline: 1.2044x; 1.0685x over previous
#include <cuda_runtime.h>
#include <math.h>

#define NN   50000
#define EE   500000
#define DD   128
#define BB   50
#define NPG  1000
#define KSEL 500
#define BK   (BB*KSEL)
#define ALPHA_F 0.6f

typedef unsigned long long ull;

#define FMA_F32X2(d, a, b, c) \
    asm("fma.rn.f32x2 %0, %1, %2, %3;" : "=l"(d) : "l"(a), "l"(b), "l"(c))
#define PACK2(d, lo, hi) \
    asm("mov.b64 %0, {%1, %2};" : "=l"(d) : "f"(lo), "f"(hi))
#define UNPACK2(lo, hi, s) \
    asm("mov.b64 {%0, %1}, %2;" : "=f"(lo), "=f"(hi) : "l"(s))

__device__ int   g_deg[NN];
__device__ float g_dinv[NN];
__device__ float g_ds[NN];
__device__ float g_zs[NN];
__device__ float g_sf[NN];
__device__ float g_ssacc[NN];
__device__ int   g_perm[BK];
__device__ float g_selscore[BK];
__device__ int   g_nodemap[NN];
__device__ int   g_off[NN];
__device__ int   g_cursor[NN];
__device__ int   g_csr[EE];
__device__ int   g_total;
__device__ int   g_bsum[512];
__device__ int   g_boff[512];

__global__ void k_init() {
    int i = blockIdx.x * blockDim.x + threadIdx.x;
    int stride = gridDim.x * blockDim.x;
    if (i == 0) g_total = 0;
    for (int t = i; t < NN; t += stride) {
        g_deg[t] = 0;
        g_ssacc[t] = 0.f;
        g_nodemap[t] = -1;
    }
}

__global__ void k_deg(const int* __restrict__ dst) {
    int i = blockIdx.x * blockDim.x + threadIdx.x;
    if (i < EE / 4) {
        int4 d4 = ((const int4*)dst)[i];
        atomicAdd(&g_deg[d4.x], 1);
        atomicAdd(&g_deg[d4.y], 1);
        atomicAdd(&g_deg[d4.z], 1);
        atomicAdd(&g_deg[d4.w], 1);
    }
}

__global__ void k_scores(const float* __restrict__ x, const float* __restrict__ Ws,
                         const float* __restrict__ Wf, const float* __restrict__ bf) {
    int warp = (blockIdx.x * blockDim.x + threadIdx.x) >> 5;
    int lane = threadIdx.x & 31;
    if (warp >= NN) return;
    float4 xv = ((const float4*)x)[warp * 32 + lane];
    float4 ws = ((const float4*)Ws)[lane];
    float4 wf = ((const float4*)Wf)[lane];
    float ds = xv.x*ws.x + xv.y*ws.y + xv.z*ws.z + xv.w*ws.w;
    float df = xv.x*wf.x + xv.y*wf.y + xv.z*wf.z + xv.w*wf.w;
    #pragma unroll
    for (int o = 16; o > 0; o >>= 1) {
        ds += __shfl_down_sync(0xffffffffu, ds, o);
        df += __shfl_down_sync(0xffffffffu, df, o);
    }
    if (lane == 0) {
        g_ds[warp] = ds;
        g_sf[warp] = df + bf[0];
    }
}

__global__ void k_offsets() {
    __shared__ int wpref[8];
    int tid = threadIdx.x;
    int n = blockIdx.x * 256 + tid;
    int d = (n < NN) ? g_deg[n] : 0;
    int lane = tid & 31, wid = tid >> 5;
    int v = d;
    #pragma unroll
    for (int o = 1; o < 32; o <<= 1) {
        int u = __shfl_up_sync(0xffffffffu, v, o);
        if (lane >= o) v += u;
    }
    if (lane == 31) wpref[wid] = v;
    __syncthreads();
    if (tid == 0) {
        int t[8], run = 0;
        #pragma unroll
        for (int w = 0; w < 8; w++) { t[w] = run; run += wpref[w]; }
        int base = atomicAdd(&g_total, run);
        #pragma unroll
        for (int w = 0; w < 8; w++) wpref[w] = base + t[w];
    }
    __syncthreads();
    int off = wpref[wid] + (v - d);
    if (n < NN) {
        g_off[n]    = off;
        g_cursor[n] = off;
        float dv = rsqrtf((float)(d + 1));
        g_dinv[n] = dv;
        g_zs[n]   = dv * g_ds[n];
    }
}

__global__ void k_csr(const int* __restrict__ src, const int* __restrict__ dst) {
    int i = blockIdx.x * blockDim.x + threadIdx.x;
    if (i < EE / 4) {
        int4 s4 = ((const int4*)src)[i];
        int4 d4 = ((const int4*)dst)[i];
        g_csr[atomicAdd(&g_cursor[d4.x], 1)] = s4.x;
        g_csr[atomicAdd(&g_cursor[d4.y], 1)] = s4.y;
        g_csr[atomicAdd(&g_cursor[d4.z], 1)] = s4.z;
        g_csr[atomicAdd(&g_cursor[d4.w], 1)] = s4.w;
    }
}

// edge scatter for structure score: ssacc[dst] += zs[src] (no CSR dependency)
__global__ void k_edge_score(const int* __restrict__ src, const int* __restrict__ dst) {
    int i = blockIdx.x * blockDim.x + threadIdx.x;
    if (i < EE / 4) {
        int4 s4 = ((const int4*)src)[i];
        int4 d4 = ((const int4*)dst)[i];
        atomicAdd(&g_ssacc[d4.x], g_zs[s4.x]);
        atomicAdd(&g_ssacc[d4.y], g_zs[s4.y]);
        atomicAdd(&g_ssacc[d4.z], g_zs[s4.z]);
        atomicAdd(&g_ssacc[d4.w], g_zs[s4.w]);
    }
}

// fused: score finalization (tanh) + per-graph rank selection
__global__ void k_topk(const float* __restrict__ bs, float* __restrict__ out,
                       long permOff, long batchOff) {
    __shared__ __align__(16) ull sk[NPG];
    __shared__ float ssc[NPG];
    int b = blockIdx.x >> 2;
    int quarter = blockIdx.x & 3;
    int tid = threadIdx.x;
    float bsv = bs[0];
    for (int i = tid; i < NPG; i += 256) {
        int n = b * NPG + i;
        float ss = g_dinv[n] * (g_ssacc[n] + g_zs[n]) + bsv;
        float sc = tanhf(ALPHA_F * ss + (1.0f - ALPHA_F) * g_sf[n]);
        ssc[i] = sc;
        int iv = __float_as_int(sc);
        unsigned u = (unsigned)iv ^ ((unsigned)(iv >> 31) | 0x80000000u);
        sk[i] = ((ull)u << 32) | (unsigned)(~i);
    }
    __syncthreads();
    int j = quarter * 256 + tid;
    if (j >= NPG) return;
    ull myk = sk[j];
    int rank = 0;
    const ulonglong2* p2 = (const ulonglong2*)sk;
    #pragma unroll 4
    for (int i2 = 0; i2 < NPG / 2; i2++) {
        ulonglong2 kv = p2[i2];
        rank += (kv.x > myk);
        rank += (kv.y > myk);
    }
    if (rank < KSEL) {
        int p  = b * NPG + j;
        int gi = b * KSEL + rank;
        g_perm[gi]     = p;
        g_selscore[gi] = ssc[j];
        g_nodemap[p]   = gi;
        out[permOff  + gi] = (float)p;
        out[batchOff + gi] = (float)b;
    }
}

// ---------------- fused gather + FMA2 GEMM (column-paired; layouts identical to R9) --
#define SA_S 132
__global__ void __launch_bounds__(256)
k_gemm(const float* __restrict__ x, const float* __restrict__ W,
       const float* __restrict__ bfu, float* __restrict__ out, long xaeOff) {
    __shared__ __align__(16) float sA[64 * SA_S];   // 33.8 KB
    __shared__ __align__(16) float sB[16 * 128];    // 8 KB

    int tid  = threadIdx.x;
    int lane = tid & 31, wid = tid >> 5;
    int row0 = blockIdx.x * 64;

    // gather: warp wid builds rows wid*8 .. wid*8+7
    #pragma unroll
    for (int i = 0; i < 8; i++) {
        int r = wid * 8 + i;
        int grow = row0 + r;
        float4 acc = make_float4(0.f, 0.f, 0.f, 0.f);
        if (grow < BK) {
            int   p   = g_perm[grow];
            float dvp = g_dinv[p];
            float4 xv = ((const float4*)x)[p * 32 + lane];
            acc = make_float4(dvp*xv.x, dvp*xv.y, dvp*xv.z, dvp*xv.w);
            int beg = g_off[p], len = g_deg[p];
            for (int base = 0; base < len; base += 32) {
                int idx = base + lane;
                int   s  = (idx < len) ? g_csr[beg + idx] : 0;
                float dv = (idx < len) ? g_dinv[s] : 0.f;
                int cnt = min(32, len - base);
                for (int j = 0; j < cnt; j++) {
                    int   sj = __shfl_sync(0xffffffffu, s,  j);
                    float dj = __shfl_sync(0xffffffffu, dv, j);
                    float4 xs = ((const float4*)x)[sj * 32 + lane];
                    acc.x += dj * xs.x;
                    acc.y += dj * xs.y;
                    acc.z += dj * xs.z;
                    acc.w += dj * xs.w;
                }
            }
            acc.x *= dvp; acc.y *= dvp; acc.z *= dvp; acc.w *= dvp;
        }
        *(float4*)&sA[r * SA_S + lane * 4] = acc;
    }
    __syncthreads();

    ull acc2[8][2];
    #pragma unroll
    for (int i = 0; i < 8; i++) { acc2[i][0] = 0ull; acc2[i][1] = 0ull; }

    int tx = lane, ty = wid;

    for (int kk = 0; kk < DD; kk += 16) {
        for (int q = tid; q < 512; q += 256) {
            int k = q >> 5, c4 = (q & 31) * 4;
            *(float4*)&sB[k * 128 + c4] = *(const float4*)&W[(long)(kk + k) * DD + c4];
        }
        __syncthreads();
        #pragma unroll
        for (int k = 0; k < 16; k++) {
            float4 b4 = *(float4*)&sB[k * 128 + tx * 4];
            ull b01, b23;
            PACK2(b01, b4.x, b4.y);
            PACK2(b23, b4.z, b4.w);
            #pragma unroll
            for (int i = 0; i < 8; i++) {
                float a = sA[(ty * 8 + i) * SA_S + kk + k];
                ull aa;
                PACK2(aa, a, a);
                FMA_F32X2(acc2[i][0], aa, b01, acc2[i][0]);
                FMA_F32X2(acc2[i][1], aa, b23, acc2[i][1]);
            }
        }
        __syncthreads();
    }

    float4 bias = *(const float4*)&bfu[tx * 4];
    #pragma unroll
    for (int i = 0; i < 8; i++) {
        int r = ty * 8 + i;
        int grow = row0 + r;
        if (grow < BK) {
            float sc = g_selscore[grow];
            float v0, v1, v2, v3;
            UNPACK2(v0, v1, acc2[i][0]);
            UNPACK2(v2, v3, acc2[i][1]);
            v0 += bias.x; v1 += bias.y; v2 += bias.z; v3 += bias.w;
            long base = (long)grow * DD + tx * 4;
            *(float4*)&out[base] = make_float4(v0*sc, v1*sc, v2*sc, v3*sc);
            *(float2*)&out[xaeOff + base]     = make_float2(v0, v1);
            *(float2*)&out[xaeOff + base + 2] = make_float2(v2, v3);
        }
    }
}

#define SCAN_T 256
#define SCAN_I 8
#define SCAN_B ((EE + SCAN_T*SCAN_I - 1) / (SCAN_T*SCAN_I))

__global__ void k_flag(const int* __restrict__ src, const int* __restrict__ dst) {
    __shared__ int wsum[8];
    int tid = threadIdx.x;
    int base = blockIdx.x * SCAN_T * SCAN_I + tid * SCAN_I;
    int cnt = 0;
    #pragma unroll
    for (int t = 0; t < SCAN_I; t++) {
        int e = base + t;
        if (e < EE && g_nodemap[src[e]] >= 0 && g_nodemap[dst[e]] >= 0) cnt++;
    }
    int lane = tid & 31, wid = tid >> 5;
    int v = cnt;
    #pragma unroll
    for (int o = 16; o > 0; o >>= 1) v += __shfl_down_sync(0xffffffffu, v, o);
    if (lane == 0) wsum[wid] = v;
    __syncthreads();
    if (tid == 0) {
        int tot = 0;
        for (int w = 0; w < 8; w++) tot += wsum[w];
        g_bsum[blockIdx.x] = tot;
    }
}

__global__ void k_scan() {
    if (threadIdx.x == 0) {
        int run = 0;
        for (int b = 0; b < SCAN_B; b++) { g_boff[b] = run; run += g_bsum[b]; }
    }
}

__global__ void k_scatter(const int* __restrict__ src, const int* __restrict__ dst,
                          float* __restrict__ out, long edgeOff, int M) {
    __shared__ int wsum[8];
    __shared__ int woff[8];
    int tid = threadIdx.x;
    int base = blockIdx.x * SCAN_T * SCAN_I + tid * SCAN_I;
    int f[SCAN_I], r[SCAN_I], c[SCAN_I];
    int cnt = 0;
    #pragma unroll
    for (int t = 0; t < SCAN_I; t++) {
        int e = base + t;
        f[t] = 0;
        if (e < EE) {
            int rr = g_nodemap[src[e]];
            int cc = g_nodemap[dst[e]];
            if (rr >= 0 && cc >= 0) { f[t] = 1; r[t] = rr; c[t] = cc; cnt++; }
        }
    }
    int lane = tid & 31, wid = tid >> 5;
    int v = cnt;
    #pragma unroll
    for (int o = 1; o < 32; o <<= 1) {
        int u = __shfl_up_sync(0xffffffffu, v, o);
        if (lane >= o) v += u;
    }
    if (lane == 31) wsum[wid] = v;
    __syncthreads();
    if (tid == 0) {
        int run = 0;
        for (int w = 0; w < 8; w++) { woff[w] = run; run += wsum[w]; }
    }
    __syncthreads();
    int pos = (v - cnt) + woff[wid] + g_boff[blockIdx.x];
    #pragma unroll
    for (int t = 0; t < SCAN_I; t++) {
        if (f[t]) {
            out[edgeOff + pos]     = (float)r[t];
            out[edgeOff + M + pos] = (float)c[t];
            pos++;
        }
    }
}

struct AsyncRes {
    cudaStream_t s1, s2;
    cudaEvent_t evRoot, evScores, evOff, evCsr, evTopk, evTail;
    AsyncRes() {
        cudaStreamCreateWithFlags(&s1, cudaStreamNonBlocking);
        cudaStreamCreateWithFlags(&s2, cudaStreamNonBlocking);
        cudaEventCreateWithFlags(&evRoot,   cudaEventDisableTiming);
        cudaEventCreateWithFlags(&evScores, cudaEventDisableTiming);
        cudaEventCreateWithFlags(&evOff,    cudaEventDisableTiming);
        cudaEventCreateWithFlags(&evCsr,    cudaEventDisableTiming);
        cudaEventCreateWithFlags(&evTopk,   cudaEventDisableTiming);
        cudaEventCreateWithFlags(&evTail,   cudaEventDisableTiming);
    }
};

extern "C" void kernel_launch(void* const* d_in, const int* in_sizes, int n_in,
                              void* d_out, int out_size) {
    const float* x    = (const float*)d_in[0];
    const int*   ei   = (const int*)d_in[1];
    const float* Ws   = (const float*)d_in[3];
    const float* bs   = (const float*)d_in[4];
    const float* Wf   = (const float*)d_in[5];
    const float* bf   = (const float*)d_in[6];
    const float* Wfu  = (const float*)d_in[7];
    const float* bfu  = (const float*)d_in[8];
    float* out = (float*)d_out;

    static AsyncRes R;

    const int* src = ei;
    const int* dst = ei + EE;

    long M = ((long)out_size - (2L * BK * DD + 2L * BK)) / 2;
    long edgeOff  = (long)BK * DD;
    long batchOff = edgeOff + 2 * M;
    long permOff  = batchOff + BK;
    long xaeOff   = permOff + BK;

    // fork: score GEMVs (need only x/weights)
    cudaEventRecord(R.evRoot, 0);
    cudaStreamWaitEvent(R.s1, R.evRoot, 0);
    k_scores<<<(NN * 32 + 255) / 256, 256, 0, R.s1>>>(x, Ws, Wf, bf);
    cudaEventRecord(R.evScores, R.s1);

    // main: degree histogram
    k_init<<<128, 256>>>();
    k_deg<<<(EE / 4 + 255) / 256, 256>>>(dst);

    // join scores; offsets fuses dinv + zs
    cudaStreamWaitEvent(0, R.evScores, 0);
    k_offsets<<<(NN + 255) / 256, 256>>>();

    // fork: CSR build on s2 (only the GEMM needs it)
    cudaEventRecord(R.evOff, 0);
    cudaStreamWaitEvent(R.s2, R.evOff, 0);
    k_csr<<<(EE / 4 + 255) / 256, 256, 0, R.s2>>>(src, dst);
    cudaEventRecord(R.evCsr, R.s2);

    // main: score aggregation (atomic scatter; no CSR dep) + fused score/topk
    k_edge_score<<<(EE / 4 + 255) / 256, 256>>>(src, dst);
    k_topk<<<BB * 4, 256>>>(bs, out, permOff, batchOff);

    // fork: edge compaction on s1 (needs nodemap only)
    cudaEventRecord(R.evTopk, 0);
    cudaStreamWaitEvent(R.s1, R.evTopk, 0);
    k_flag<<<SCAN_B, SCAN_T, 0, R.s1>>>(src, dst);
    k_scan<<<1, 32, 0, R.s1>>>();
    k_scatter<<<SCAN_B, SCAN_T, 0, R.s1>>>(src, dst, out, edgeOff, (int)M);
    cudaEventRecord(R.evTail, R.s1);

    // main: fused gather + GEMM (needs CSR + perm)
    cudaStreamWaitEvent(0, R.evCsr, 0);
    k_gemm<<<(BK + 63) / 64, 256>>>(x, Wfu, bfu, out, xaeOff);

    cudaStreamWaitEvent(0, R.evTail, 0);
}